// round 13
// baseline (speedup 1.0000x reference)
#include <cuda_runtime.h>
#include <math.h>

#define NMAX 100000
#define EMAX 1600000
#define BN_EPS 1e-5f

// ---------------- scratch (static device globals; no allocations) ----------------
__device__ int    g_deg[NMAX];
__device__ int    g_off[NMAX + 1];
__device__ int    g_cur[NMAX];
__device__ int    g_csr[EMAX];
__device__ int    g_bsum2[256];       // inclusive chained block sums
__device__ int    g_flag[256];        // chained-scan ready flags (zeroed each replay)
__device__ float  g_dinv[NMAX];
__device__ float  g_hs[NMAX * 64];    // pre-scaled linear output (x_s = dinv * (xW^T + b))
__device__ float  g_agg[NMAX * 64];   // aggregated GCN-layer output
__device__ double g_csum[64];
__device__ double g_csq[64];
__device__ float  g_sc[64];           // BN scale  (g * rsqrt(var+eps))
__device__ float  g_sh[64];           // BN shift  (beta - mu * scale)

// packed f32x2 FMA (Blackwell; ptxas never auto-fuses — PTX only)
#define FMA_F32X2(d, a, b, c) \
    asm("fma.rn.f32x2 %0, %1, %2, %3;" : "=l"(d) : "l"(a), "l"(b), "l"(c))

// ---------------- preprocessing ----------------
// fused init: zero degrees + BN stats (layer 1) + chained-scan flags
__global__ void init_kernel(int n) {
    int i = blockIdx.x * blockDim.x + threadIdx.x;
    if (i < n) g_deg[i] = 0;
    if (blockIdx.x == 0) {
        if (threadIdx.x < 64) { g_csum[threadIdx.x] = 0.0; g_csq[threadIdx.x] = 0.0; }
        if (threadIdx.x < 256) g_flag[threadIdx.x] = 0;
    }
}

__global__ void count_deg(const int* __restrict__ dst, int e) {
    int i = blockIdx.x * blockDim.x + threadIdx.x;
    if (i < e) atomicAdd(&g_deg[dst[i]], 1);
}

// single-pass chained scan over g_deg -> g_off/g_cur (exclusive) + g_dinv.
// All nb (<=148) blocks are co-resident, so the carry spin cannot deadlock.
__global__ void scan_chained(int n, int nb) {
    __shared__ int s[1024];
    __shared__ int carry_s;
    int tid = threadIdx.x, b = blockIdx.x;
    int i = b * 1024 + tid;
    int v = (i < n) ? g_deg[i] : 0;
    s[tid] = v;
    __syncthreads();
    for (int d = 1; d < 1024; d <<= 1) {
        int t = (tid >= d) ? s[tid - d] : 0;
        __syncthreads();
        s[tid] += t;
        __syncthreads();
    }
    int total = s[1023];
    if (tid == 0) {
        int c = 0;
        if (b > 0) {
            while (((volatile int*)g_flag)[b - 1] == 0) { }
            __threadfence();
            c = g_bsum2[b - 1];
        }
        g_bsum2[b] = c + total;
        __threadfence();
        ((volatile int*)g_flag)[b] = 1;
        carry_s = c;
        if (b == nb - 1) g_off[n] = c + total;
    }
    __syncthreads();
    if (i < n) {
        int ex = carry_s + s[tid] - v;   // exclusive prefix
        g_off[i] = ex;
        g_cur[i] = ex;
        g_dinv[i] = rsqrtf((float)(v + 1));   // +1 self-loop
    }
}

__global__ void fill_csr(const int* __restrict__ src, const int* __restrict__ dst, int e) {
    int i = blockIdx.x * blockDim.x + threadIdx.x;
    if (i < e) {
        int p = atomicAdd(&g_cur[dst[i]], 1);
        g_csr[p] = src[i];
    }
}

__global__ void zero_stats() {
    int t = threadIdx.x;
    if (t < 64) { g_csum[t] = 0.0; g_csq[t] = 0.0; }
}

__global__ void bn_finalize(const float* __restrict__ g, const float* __restrict__ be, float invn) {
    int t = threadIdx.x;
    if (t < 64) {
        double mu  = g_csum[t] * (double)invn;
        double var = g_csq[t] * (double)invn - mu * mu;
        float rs = (float)(1.0 / sqrt(var + (double)BN_EPS));
        float sc = g[t] * rs;
        g_sc[t] = sc;
        g_sh[t] = be[t] - (float)mu * sc;
    }
}

// ---------------- linear: h_s[r] = dinv[r] * (act(in[r]) @ W^T + b) ----------------
// thread-per-row; 64 outputs as 32 packed f32x2 accumulators (FFMA2 halves FMA
// instruction count, bitwise-identical math). W staged in smem as feature-pairs.
template <int K, bool BN>
__global__ void __launch_bounds__(128) linear_kernel(
    const float* __restrict__ in, const float* __restrict__ W,
    const float* __restrict__ b, float* __restrict__ out, int n)
{
    __shared__ float2 Wp[32 * K];   // Wp[p*K+k] = (W[2p][k], W[2p+1][k])
    __shared__ float sb[64];
    __shared__ float ssc[64];
    __shared__ float ssh[64];
    int tid = threadIdx.x;

    for (int idx = tid; idx < 32 * K; idx += 128) {
        int p = idx / K, k = idx - p * K;
        Wp[idx] = make_float2(W[(2 * p) * K + k], W[(2 * p + 1) * K + k]);
    }
    if (tid < 64) {
        sb[tid] = b[tid];
        if (BN) { ssc[tid] = g_sc[tid]; ssh[tid] = g_sh[tid]; }
    }
    __syncthreads();

    int r = blockIdx.x * 128 + tid;
    if (r >= n) return;

    unsigned long long acc[32];
#pragma unroll
    for (int p = 0; p < 32; p++)
        asm("mov.b64 %0, {%1, %2};" : "=l"(acc[p]) : "f"(sb[2 * p]), "f"(sb[2 * p + 1]));

    const float4* xr4 = (const float4*)(in + (long)r * K);
#pragma unroll 1
    for (int kb = 0; kb < K; kb += 8) {
        float xr[8];
        float4 v0 = xr4[kb / 4];
        float4 v1 = xr4[kb / 4 + 1];
        xr[0] = v0.x; xr[1] = v0.y; xr[2] = v0.z; xr[3] = v0.w;
        xr[4] = v1.x; xr[5] = v1.y; xr[6] = v1.z; xr[7] = v1.w;
        if (BN) {
#pragma unroll
            for (int kk = 0; kk < 8; kk++)
                xr[kk] = fmaxf(fmaf(xr[kk], ssc[kb + kk], ssh[kb + kk]), 0.0f);
        }
        unsigned long long xx[8];
#pragma unroll
        for (int kk = 0; kk < 8; kk++)
            asm("mov.b64 %0, {%1, %1};" : "=l"(xx[kk]) : "f"(xr[kk]));
#pragma unroll
        for (int p = 0; p < 32; p++) {
            const ulonglong2* w2 = (const ulonglong2*)(&Wp[p * K + kb]);
            ulonglong2 wa = w2[0];
            ulonglong2 wb = w2[1];
            ulonglong2 wc = w2[2];
            ulonglong2 wd = w2[3];
            FMA_F32X2(acc[p], xx[0], wa.x, acc[p]);
            FMA_F32X2(acc[p], xx[1], wa.y, acc[p]);
            FMA_F32X2(acc[p], xx[2], wb.x, acc[p]);
            FMA_F32X2(acc[p], xx[3], wb.y, acc[p]);
            FMA_F32X2(acc[p], xx[4], wc.x, acc[p]);
            FMA_F32X2(acc[p], xx[5], wc.y, acc[p]);
            FMA_F32X2(acc[p], xx[6], wd.x, acc[p]);
            FMA_F32X2(acc[p], xx[7], wd.y, acc[p]);
        }
    }

    float di = g_dinv[r];
    float2* o2 = (float2*)(out + (long)r * 64);
#pragma unroll
    for (int p = 0; p < 32; p++) {
        float lo, hi;
        asm("mov.b64 {%0, %1}, %2;" : "=f"(lo), "=f"(hi) : "l"(acc[p]));
        o2[p] = make_float2(lo * di, hi * di);
    }
}

// ---------------- aggregation: out[i] = dinv[i]*(hs[i] + sum_{src in N(i)} hs[src]) --------
// warp per node; lane owns features {2*lane, 2*lane+1}. 4 independent accumulator
// chains in the gather loop guarantee MLP>=4 per warp. MODE 0: + BN column stats.
// MODE 2: + fused log_softmax, writes final output.
template <int MODE>
__global__ void __launch_bounds__(512) agg_kernel(
    const float* __restrict__ hs, float* __restrict__ out, int n)
{
    constexpr bool STATS = (MODE == 0);
    constexpr bool SMAX  = (MODE == 2);
    __shared__ float ssum[64];
    __shared__ float ssq[64];
    int tid = threadIdx.x;
    if (STATS) {
        if (tid < 64) { ssum[tid] = 0.0f; ssq[tid] = 0.0f; }
        __syncthreads();
    }
    int node = (blockIdx.x * 512 + tid) >> 5;
    int lane = tid & 31;
    if (node < n) {
        const float2* h2 = (const float2*)hs;
        float2 a0 = h2[(long)node * 32 + lane];        // self-loop term
        float2 a1 = make_float2(0.0f, 0.0f);
        float2 a2 = make_float2(0.0f, 0.0f);
        float2 a3 = make_float2(0.0f, 0.0f);
        int s0 = g_off[node], s1 = g_off[node + 1];
        for (int base = s0; base < s1; base += 32) {
            int j = base + lane;
            int se = (j < s1) ? g_csr[j] : 0;
            int cnt = min(32, s1 - base);
            int t = 0;
            for (; t + 4 <= cnt; t += 4) {
                int i0 = __shfl_sync(0xffffffffu, se, t);
                int i1 = __shfl_sync(0xffffffffu, se, t + 1);
                int i2 = __shfl_sync(0xffffffffu, se, t + 2);
                int i3 = __shfl_sync(0xffffffffu, se, t + 3);
                float2 v0 = h2[(long)i0 * 32 + lane];
                float2 v1 = h2[(long)i1 * 32 + lane];
                float2 v2 = h2[(long)i2 * 32 + lane];
                float2 v3 = h2[(long)i3 * 32 + lane];
                a0.x += v0.x; a0.y += v0.y;
                a1.x += v1.x; a1.y += v1.y;
                a2.x += v2.x; a2.y += v2.y;
                a3.x += v3.x; a3.y += v3.y;
            }
            for (; t < cnt; t++) {
                int s = __shfl_sync(0xffffffffu, se, t);
                float2 v = h2[(long)s * 32 + lane];
                a0.x += v.x; a0.y += v.y;
            }
        }
        float2 acc;
        acc.x = (a0.x + a1.x) + (a2.x + a3.x);
        acc.y = (a0.y + a1.y) + (a2.y + a3.y);
        float di = g_dinv[node];
        acc.x *= di; acc.y *= di;
        if (SMAX) {
            float m = fmaxf(acc.x, acc.y);
#pragma unroll
            for (int o = 16; o > 0; o >>= 1) m = fmaxf(m, __shfl_xor_sync(0xffffffffu, m, o));
            float sum = expf(acc.x - m) + expf(acc.y - m);
#pragma unroll
            for (int o = 16; o > 0; o >>= 1) sum += __shfl_xor_sync(0xffffffffu, sum, o);
            float l = m + logf(sum);
            float2 r; r.x = acc.x - l; r.y = acc.y - l;
            ((float2*)out)[(long)node * 32 + lane] = r;
        } else {
            ((float2*)out)[(long)node * 32 + lane] = acc;
            if (STATS) {
                atomicAdd(&ssum[2 * lane + 0], acc.x);
                atomicAdd(&ssum[2 * lane + 1], acc.y);
                atomicAdd(&ssq[2 * lane + 0], acc.x * acc.x);
                atomicAdd(&ssq[2 * lane + 1], acc.y * acc.y);
            }
        }
    }
    if (STATS) {
        __syncthreads();
        if (tid < 64) {
            atomicAdd(&g_csum[tid], (double)ssum[tid]);
            atomicAdd(&g_csq[tid],  (double)ssq[tid]);
        }
    }
}

// ---------------- launch ----------------
extern "C" void kernel_launch(void* const* d_in, const int* in_sizes, int n_in,
                              void* d_out, int out_size)
{
    const float* x   = (const float*)d_in[0];
    const int*   ei  = (const int*)  d_in[1];
    const float* W1  = (const float*)d_in[2];
    const float* b1  = (const float*)d_in[3];
    const float* g1  = (const float*)d_in[4];
    const float* be1 = (const float*)d_in[5];
    const float* W2  = (const float*)d_in[6];
    const float* b2  = (const float*)d_in[7];
    const float* g2  = (const float*)d_in[8];
    const float* be2 = (const float*)d_in[9];
    const float* W3  = (const float*)d_in[10];
    const float* b3  = (const float*)d_in[11];
    float* out = (float*)d_out;

    int n = in_sizes[0] / 128;
    int e = in_sizes[1] / 2;
    const int* src = ei;
    const int* dst = ei + e;

    float* hs;  cudaGetSymbolAddress((void**)&hs,  g_hs);
    float* agg; cudaGetSymbolAddress((void**)&agg, g_agg);

    int nb = (n + 1023) / 1024;
    int eb = (e + 255) / 256;
    int vb = (n + 255) / 256;
    int lb = (n + 127) / 128;
    int ab = ((long)n * 32 + 511) / 512;
    float invn = 1.0f / (float)n;

    // prep: degrees -> chained scan (offsets + dinv) ; CSR fill after linear1
    init_kernel<<<vb, 256>>>(n);
    count_deg<<<eb, 256>>>(dst, e);
    scan_chained<<<nb, 1024>>>(n, nb);

    // layer 1: x(128) -> 64   (linear at graph index 3 for the ncu capture slot)
    linear_kernel<128, false><<<lb, 128>>>(x, W1, b1, hs, n);
    fill_csr<<<eb, 256>>>(src, dst, e);
    agg_kernel<0><<<ab, 512>>>(hs, agg, n);
    bn_finalize<<<1, 64>>>(g1, be1, invn);

    // layer 2: (BN+ReLU fused into input read)
    linear_kernel<64, true><<<lb, 128>>>(agg, W2, b2, hs, n);
    zero_stats<<<1, 64>>>();
    agg_kernel<0><<<ab, 512>>>(hs, agg, n);
    bn_finalize<<<1, 64>>>(g2, be2, invn);

    // layer 3: + fused log_softmax into final aggregation
    linear_kernel<64, true><<<lb, 128>>>(agg, W3, b3, hs, n);
    agg_kernel<2><<<ab, 512>>>(hs, out, n);
}

// round 16
// speedup vs baseline: 1.2963x; 1.2963x over previous
#include <cuda_runtime.h>
#include <math.h>

#define NMAX 100000
#define EMAX 1600000
#define BN_EPS 1e-5f
#define KC 32

// ---------------- scratch (static device globals; no allocations) ----------------
__device__ int    g_deg[NMAX];
__device__ int    g_off[NMAX + 1];
__device__ int    g_cur[NMAX];
__device__ int    g_csr[EMAX];
__device__ int    g_bsum2[256];       // inclusive chained block sums
__device__ int    g_flag[256];        // chained-scan ready flags (zeroed each replay)
__device__ float  g_dinv[NMAX];
__device__ float  g_hs[NMAX * 64];
__device__ float  g_agg[NMAX * 64];
__device__ double g_csum[64];
__device__ double g_csq[64];
__device__ float  g_sc[64];
__device__ float  g_sh[64];

// packed f32x2 FMA (Blackwell; PTX-only pattern)
#define FMA_F32X2(d, a, b, c) \
    asm("fma.rn.f32x2 %0, %1, %2, %3;" : "=l"(d) : "l"(a), "l"(b), "l"(c))
#define PACK2(d, lo, hi) \
    asm("mov.b64 %0, {%1, %2};" : "=l"(d) : "f"(lo), "f"(hi))
#define PACKDUP(d, v) \
    asm("mov.b64 %0, {%1, %1};" : "=l"(d) : "f"(v))
#define UNPACK2(lo, hi, d) \
    asm("mov.b64 {%0, %1}, %2;" : "=f"(lo), "=f"(hi) : "l"(d))

// ---------------- preprocessing ----------------
__global__ void init_kernel(int n) {
    int i = blockIdx.x * blockDim.x + threadIdx.x;
    if (i < n) g_deg[i] = 0;
    if (blockIdx.x == 0) {
        if (threadIdx.x < 64) { g_csum[threadIdx.x] = 0.0; g_csq[threadIdx.x] = 0.0; }
        if (threadIdx.x < 256) g_flag[threadIdx.x] = 0;
    }
}

__global__ void count_deg(const int* __restrict__ dst, int e) {
    int i = blockIdx.x * blockDim.x + threadIdx.x;
    if (i < e) atomicAdd(&g_deg[dst[i]], 1);
}

// single-pass chained scan, 4 elems/thread (4096/block, 25 blocks for n=100k).
// All blocks co-resident in wave 1 -> carry spin cannot deadlock.
__global__ void scan_chained(int n, int nb) {
    __shared__ int s[1024];
    __shared__ int carry_s;
    int tid = threadIdx.x, b = blockIdx.x;
    int i0 = b * 4096 + tid * 4;
    int v[4];
#pragma unroll
    for (int q = 0; q < 4; q++) { int i = i0 + q; v[q] = (i < n) ? g_deg[i] : 0; }
    int tsum = v[0] + v[1] + v[2] + v[3];
    s[tid] = tsum;
    __syncthreads();
    for (int d = 1; d < 1024; d <<= 1) {
        int t = (tid >= d) ? s[tid - d] : 0;
        __syncthreads();
        s[tid] += t;
        __syncthreads();
    }
    int total = s[1023];
    if (tid == 0) {
        int c = 0;
        if (b > 0) {
            while (((volatile int*)g_flag)[b - 1] == 0) { }
            __threadfence();
            c = g_bsum2[b - 1];
        }
        g_bsum2[b] = c + total;
        __threadfence();
        ((volatile int*)g_flag)[b] = 1;
        carry_s = c;
        if (b == nb - 1) g_off[n] = c + total;
    }
    __syncthreads();
    int ex = carry_s + s[tid] - tsum;
#pragma unroll
    for (int q = 0; q < 4; q++) {
        int i = i0 + q;
        if (i < n) {
            g_off[i] = ex;
            g_cur[i] = ex;
            g_dinv[i] = rsqrtf((float)(v[q] + 1));   // +1 self-loop
        }
        ex += v[q];
    }
}

__global__ void fill_csr(const int* __restrict__ src, const int* __restrict__ dst, int e) {
    int i = blockIdx.x * blockDim.x + threadIdx.x;
    if (i < e) {
        int p = atomicAdd(&g_cur[dst[i]], 1);
        g_csr[p] = src[i];
    }
}

__global__ void zero_stats() {
    int t = threadIdx.x;
    if (t < 64) { g_csum[t] = 0.0; g_csq[t] = 0.0; }
}

__global__ void bn_finalize(const float* __restrict__ g, const float* __restrict__ be, float invn) {
    int t = threadIdx.x;
    if (t < 64) {
        double mu  = g_csum[t] * (double)invn;
        double var = g_csq[t] * (double)invn - mu * mu;
        float rs = (float)(1.0 / sqrt(var + (double)BN_EPS));
        float sc = g[t] * rs;
        g_sc[t] = sc;
        g_sh[t] = be[t] - (float)mu * sc;
    }
}

// ---------------- linear: h_s[r] = dinv[r] * (act(in[r]) @ W^T + b) ----------------
// Warp-cooperative tile: block=256 (8 warps) covers 128 rows; warp owns 16 rows
// (8 row-pairs); lane owns outputs (2*lane, 2*lane+1). Row-pair FFMA2: one packed
// {xA,xB} feeds two FFMA2s -> fma-pipe instruction count halved vs scalar.
template <int K, bool BN>
__global__ void __launch_bounds__(256) linear_kernel(
    const float* __restrict__ in, const float* __restrict__ W,
    const float* __restrict__ b, float* __restrict__ out, int n)
{
    __shared__ float4 xs4[128][KC / 4];   // 16KB: 128 rows x 32 k
    __shared__ float2 wt2s[KC][32];       // 8KB:  wt2s[k][j] = (W[2j][k], W[2j+1][k])
    __shared__ float ssc[64], ssh[64];
    int tid  = threadIdx.x;
    int lane = tid & 31, wid = tid >> 5;
    int row0 = blockIdx.x * 128;
    int rb   = wid * 16;

    if (BN && tid < 64) { ssc[tid] = g_sc[tid]; ssh[tid] = g_sh[tid]; }

    unsigned long long acc[16];
    {
        float b0 = b[2 * lane], b1 = b[2 * lane + 1];
        unsigned long long p0, p1;
        PACKDUP(p0, b0);
        PACKDUP(p1, b1);
#pragma unroll
        for (int p = 0; p < 8; p++) { acc[2 * p] = p0; acc[2 * p + 1] = p1; }
    }

#pragma unroll 1
    for (int kc = 0; kc < K; kc += KC) {
        __syncthreads();   // smem reuse + BN table visibility
        // stage x tile (2 threads per row, 4 float4 each)
        {
            int r = tid >> 1;
            int h = (tid & 1) * 4;
            int row = row0 + r;
            const float4* src = (const float4*)(in + (long)row * K + kc);
#pragma unroll
            for (int q = 0; q < 4; q++) {
                float4 v = (row < n) ? src[h + q] : make_float4(0.f, 0.f, 0.f, 0.f);
                if (BN) {
                    int kb = kc + (h + q) * 4;
                    v.x = fmaxf(fmaf(v.x, ssc[kb + 0], ssh[kb + 0]), 0.f);
                    v.y = fmaxf(fmaf(v.y, ssc[kb + 1], ssh[kb + 1]), 0.f);
                    v.z = fmaxf(fmaf(v.z, ssc[kb + 2], ssh[kb + 2]), 0.f);
                    v.w = fmaxf(fmaf(v.w, ssc[kb + 3], ssh[kb + 3]), 0.f);
                }
                xs4[r][h + q] = v;
            }
        }
        // stage W pair tile
        {
#pragma unroll
            for (int q = 0; q < 4; q++) {
                int idx = tid * 4 + q;          // 0..1023
                int k = idx >> 5, j = idx & 31;
                wt2s[k][j] = make_float2(W[(2 * j) * K + kc + k],
                                         W[(2 * j + 1) * K + kc + k]);
            }
        }
        __syncthreads();
        // compute
#pragma unroll
        for (int k4 = 0; k4 < KC / 4; k4++) {
            unsigned long long w0d[4], w1d[4];
#pragma unroll
            for (int i = 0; i < 4; i++) {
                float2 wt = wt2s[k4 * 4 + i][lane];
                PACKDUP(w0d[i], wt.x);
                PACKDUP(w1d[i], wt.y);
            }
#pragma unroll
            for (int p = 0; p < 8; p++) {
                float4 xa = xs4[rb + 2 * p][k4];
                float4 xb = xs4[rb + 2 * p + 1][k4];
                unsigned long long x0, x1, x2, x3;
                PACK2(x0, xa.x, xb.x);
                FMA_F32X2(acc[2 * p],     x0, w0d[0], acc[2 * p]);
                FMA_F32X2(acc[2 * p + 1], x0, w1d[0], acc[2 * p + 1]);
                PACK2(x1, xa.y, xb.y);
                FMA_F32X2(acc[2 * p],     x1, w0d[1], acc[2 * p]);
                FMA_F32X2(acc[2 * p + 1], x1, w1d[1], acc[2 * p + 1]);
                PACK2(x2, xa.z, xb.z);
                FMA_F32X2(acc[2 * p],     x2, w0d[2], acc[2 * p]);
                FMA_F32X2(acc[2 * p + 1], x2, w1d[2], acc[2 * p + 1]);
                PACK2(x3, xa.w, xb.w);
                FMA_F32X2(acc[2 * p],     x3, w0d[3], acc[2 * p]);
                FMA_F32X2(acc[2 * p + 1], x3, w1d[3], acc[2 * p + 1]);
            }
        }
    }
    // write out (rowA = lo halves, rowB = hi halves), scaled by dinv
#pragma unroll
    for (int p = 0; p < 8; p++) {
        int rowA = row0 + rb + 2 * p;
        int rowB = rowA + 1;
        float a0, a1, c0, c1;
        UNPACK2(a0, c0, acc[2 * p]);
        UNPACK2(a1, c1, acc[2 * p + 1]);
        if (rowA < n) {
            float d = g_dinv[rowA];
            ((float2*)(out + (long)rowA * 64))[lane] = make_float2(a0 * d, a1 * d);
        }
        if (rowB < n) {
            float d = g_dinv[rowB];
            ((float2*)(out + (long)rowB * 64))[lane] = make_float2(c0 * d, c1 * d);
        }
    }
}

// ---------------- aggregation (unchanged from validated R11 code) ----------------
template <int MODE>
__global__ void __launch_bounds__(512) agg_kernel(
    const float* __restrict__ hs, float* __restrict__ out, int n)
{
    constexpr bool STATS = (MODE == 0);
    constexpr bool SMAX  = (MODE == 2);
    __shared__ float ssum[64];
    __shared__ float ssq[64];
    int tid = threadIdx.x;
    if (STATS) {
        if (tid < 64) { ssum[tid] = 0.0f; ssq[tid] = 0.0f; }
        __syncthreads();
    }
    int node = (blockIdx.x * 512 + tid) >> 5;
    int lane = tid & 31;
    if (node < n) {
        const float2* h2 = (const float2*)hs;
        float2 a0 = h2[(long)node * 32 + lane];
        float2 a1 = make_float2(0.0f, 0.0f);
        float2 a2 = make_float2(0.0f, 0.0f);
        float2 a3 = make_float2(0.0f, 0.0f);
        int s0 = g_off[node], s1 = g_off[node + 1];
        for (int base = s0; base < s1; base += 32) {
            int j = base + lane;
            int se = (j < s1) ? g_csr[j] : 0;
            int cnt = min(32, s1 - base);
            int t = 0;
            for (; t + 4 <= cnt; t += 4) {
                int i0 = __shfl_sync(0xffffffffu, se, t);
                int i1 = __shfl_sync(0xffffffffu, se, t + 1);
                int i2 = __shfl_sync(0xffffffffu, se, t + 2);
                int i3 = __shfl_sync(0xffffffffu, se, t + 3);
                float2 v0 = h2[(long)i0 * 32 + lane];
                float2 v1 = h2[(long)i1 * 32 + lane];
                float2 v2 = h2[(long)i2 * 32 + lane];
                float2 v3 = h2[(long)i3 * 32 + lane];
                a0.x += v0.x; a0.y += v0.y;
                a1.x += v1.x; a1.y += v1.y;
                a2.x += v2.x; a2.y += v2.y;
                a3.x += v3.x; a3.y += v3.y;
            }
            for (; t < cnt; t++) {
                int s = __shfl_sync(0xffffffffu, se, t);
                float2 v = h2[(long)s * 32 + lane];
                a0.x += v.x; a0.y += v.y;
            }
        }
        float2 acc;
        acc.x = (a0.x + a1.x) + (a2.x + a3.x);
        acc.y = (a0.y + a1.y) + (a2.y + a3.y);
        float di = g_dinv[node];
        acc.x *= di; acc.y *= di;
        if (SMAX) {
            float m = fmaxf(acc.x, acc.y);
#pragma unroll
            for (int o = 16; o > 0; o >>= 1) m = fmaxf(m, __shfl_xor_sync(0xffffffffu, m, o));
            float sum = expf(acc.x - m) + expf(acc.y - m);
#pragma unroll
            for (int o = 16; o > 0; o >>= 1) sum += __shfl_xor_sync(0xffffffffu, sum, o);
            float l = m + logf(sum);
            float2 r; r.x = acc.x - l; r.y = acc.y - l;
            ((float2*)out)[(long)node * 32 + lane] = r;
        } else {
            ((float2*)out)[(long)node * 32 + lane] = acc;
            if (STATS) {
                atomicAdd(&ssum[2 * lane + 0], acc.x);
                atomicAdd(&ssum[2 * lane + 1], acc.y);
                atomicAdd(&ssq[2 * lane + 0], acc.x * acc.x);
                atomicAdd(&ssq[2 * lane + 1], acc.y * acc.y);
            }
        }
    }
    if (STATS) {
        __syncthreads();
        if (tid < 64) {
            atomicAdd(&g_csum[tid], (double)ssum[tid]);
            atomicAdd(&g_csq[tid],  (double)ssq[tid]);
        }
    }
}

// ---------------- launch ----------------
extern "C" void kernel_launch(void* const* d_in, const int* in_sizes, int n_in,
                              void* d_out, int out_size)
{
    const float* x   = (const float*)d_in[0];
    const int*   ei  = (const int*)  d_in[1];
    const float* W1  = (const float*)d_in[2];
    const float* b1  = (const float*)d_in[3];
    const float* g1  = (const float*)d_in[4];
    const float* be1 = (const float*)d_in[5];
    const float* W2  = (const float*)d_in[6];
    const float* b2  = (const float*)d_in[7];
    const float* g2  = (const float*)d_in[8];
    const float* be2 = (const float*)d_in[9];
    const float* W3  = (const float*)d_in[10];
    const float* b3  = (const float*)d_in[11];
    float* out = (float*)d_out;

    int n = in_sizes[0] / 128;
    int e = in_sizes[1] / 2;
    const int* src = ei;
    const int* dst = ei + e;

    float* hs;  cudaGetSymbolAddress((void**)&hs,  g_hs);
    float* agg; cudaGetSymbolAddress((void**)&agg, g_agg);

    int nb = (n + 4095) / 4096;
    int eb = (e + 255) / 256;
    int vb = (n + 255) / 256;
    int lb = (n + 127) / 128;
    int ab = ((long)n * 32 + 511) / 512;
    float invn = 1.0f / (float)n;

    // prep
    init_kernel<<<vb, 256>>>(n);
    count_deg<<<eb, 256>>>(dst, e);
    scan_chained<<<nb, 1024>>>(n, nb);

    // layer 1 (linear at graph index 3 -> ncu capture slot)
    linear_kernel<128, false><<<lb, 256>>>(x, W1, b1, hs, n);
    fill_csr<<<eb, 256>>>(src, dst, e);
    agg_kernel<0><<<ab, 512>>>(hs, agg, n);
    bn_finalize<<<1, 64>>>(g1, be1, invn);

    // layer 2
    linear_kernel<64, true><<<lb, 256>>>(agg, W2, b2, hs, n);
    zero_stats<<<1, 64>>>();
    agg_kernel<0><<<ab, 512>>>(hs, agg, n);
    bn_finalize<<<1, 64>>>(g2, be2, invn);

    // layer 3
    linear_kernel<64, true><<<lb, 256>>>(agg, W3, b3, hs, n);
    agg_kernel<2><<<ab, 512>>>(hs, out, n);
}